// round 17
// baseline (speedup 1.0000x reference)
#include <cuda_runtime.h>
#include <cstdint>

// Block-diagonal grouped conv2d: 64 groups, 4 in-ch -> 4 out-ch per group, 3x3, pad 1.
// x:   (32, 256, 128, 128) fp32, channel index = ci*64 + head
// w:   (64, 4, 4, 3, 3)          w[head][co][ci][ky][kx]
// b:   (64, 4)
// out: (32, 256, 128, 128) fp32, channel index = co*64 + head
//
// v17: cross-tile cp.async pipeline. CTA = (b, head, 4 row-tiles). Two
//      ci-half buffers (ci{0,1} / ci{2,3}) ping-pong across 8 half-phases;
//      compute of half p overlaps DRAM streaming of half p+1; prefetch p+2
//      issued after compute p. Only the prologue fill is exposed.
//      v12 compute core: 2-row weight-amortized co-pair f32x2, shuffle edges.

#define TY 8
#define SROWS (TY + 2)               // 10
#define SROW_P 132
#define PLANE_P (SROWS * SROW_P)     // 1320
#define HBUF (2 * PLANE_P)           // half-buffer: 2 ci planes (2640 floats)
#define S_IN_FLOATS (2 * HBUF)       // 5280 (same as v12)
#define THREADS 128
#define H 128
#define W 128
#define PLANE (H * W)
#define NTILE 4                      // row-tiles per CTA
// s_in + 72 weight u64 + 2 bias u64
#define SMEM_BYTES (S_IN_FLOATS * 4 + 74 * 8)

typedef unsigned long long u64;

__device__ __forceinline__ u64 pk(float lo, float hi) {
    u64 r; asm("mov.b64 %0, {%1, %2};" : "=l"(r) : "f"(lo), "f"(hi)); return r;
}
__device__ __forceinline__ void upk(u64 v, float &lo, float &hi) {
    asm("mov.b64 {%0, %1}, %2;" : "=f"(lo), "=f"(hi) : "l"(v));
}
// d += a*b  (packed 2x fp32)
__device__ __forceinline__ void ffma2(u64 &d, u64 a, u64 b) {
    asm("fma.rn.f32x2 %0, %1, %2, %0;" : "+l"(d) : "l"(a), "l"(b));
}
__device__ __forceinline__ void cpasync16(uint32_t saddr, const float* g, bool pred) {
    int sz = pred ? 16 : 0;
    asm volatile("cp.async.cg.shared.global [%0], [%1], 16, %2;\n"
                 :: "r"(saddr), "l"(g), "r"(sz));
}

__global__ __launch_bounds__(THREADS, 8)
void bdconv_kernel(const float* __restrict__ x, const float* __restrict__ w,
                   const float* __restrict__ bias, float* __restrict__ out) {
    extern __shared__ __align__(16) float smem[];
    float* s_in = smem;                          // 2 half-buffers
    u64*   s_w  = (u64*)(smem + S_IN_FLOATS);    // [ci][ky*3+kx][cp] co-pair
    u64*   s_b  = s_w + 72;                      // [cp]

    const int blk  = blockIdx.x;
    const int sup  = blk & 3;           // super-tile: rows [sup*32, sup*32+32)
    const int head = (blk >> 2) & 63;
    const int b    = blk >> 8;
    const int tid  = threadIdx.x;
    const int wrp  = tid >> 5;
    const int lane = tid & 31;
    const int xo   = lane << 2;

    // staging geometry (4 warps x 5 rows = 20 rows = 2 ci planes x 10)
    const float* xg = x + ((long long)b * 256 + head) * PLANE + xo;
    const uint32_t s0 = (uint32_t)__cvta_generic_to_shared(s_in) + (uint32_t)(xo * 4);

    // ---- stage a half: tile t (y0 = (sup*4+t)*8), ci-half h, into buffer h ----
    // (buffer index == ci-half index always)
    #define STAGE_HALF(t, h)                                                     \
    {                                                                            \
        const int y0t = ((sup << 2) + (t)) << 3;                                 \
        const uint32_t sb = s0 + (uint32_t)((h) * HBUF * 4);                     \
        const float* xh = xg + (2 * (h)) * (64 * PLANE);                         \
        _Pragma("unroll")                                                        \
        for (int k = 0; k < 5; k++) {                                            \
            const int rr = wrp + (k << 2);          /* 0..19 */                  \
            const int cl = rr / SROWS;              /* 0..1  */                  \
            const int r  = rr - cl * SROWS;                                      \
            const int y  = y0t - 1 + r;                                          \
            const bool ok = (y >= 0) && (y < H);                                 \
            const int yc = ok ? y : 0;                                           \
            cpasync16(sb + (uint32_t)((cl * PLANE_P + r * SROW_P) * 4),          \
                      xh + cl * (64 * PLANE) + yc * W, ok);                      \
        }                                                                        \
        asm volatile("cp.async.commit_group;\n");                                \
    }

    // prologue: fill phases 0 and 1
    STAGE_HALF(0, 0)
    STAGE_HALF(0, 1)

    // ---- stage weights as co-pair float2 + bias pairs ----
    if (tid < 72) {
        const int cp  = tid & 1;
        const int t9  = (tid >> 1) % 9;
        const int ci  = (tid >> 1) / 9;
        const float w0 = w[((head * 4 + 2 * cp)     * 4 + ci) * 9 + t9];
        const float w1 = w[((head * 4 + 2 * cp + 1) * 4 + ci) * 9 + t9];
        s_w[(ci * 9 + t9) * 2 + cp] = pk(w0, w1);
    }
    if (tid < 2)
        s_b[tid] = pk(bias[head * 4 + 2 * tid], bias[head * 4 + 2 * tid + 1]);

    const float* plbase = s_in + (2 * wrp) * SROW_P + xo;
    float* outg = out + ((long long)b * 256 + head) * (long long)PLANE + xo;

    u64 acc0[2][4], acc1[2][4];

    #pragma unroll 1
    for (int p = 0; p < 2 * NTILE; p++) {
        const int h = p & 1;            // ci-half == buffer index
        const int t = p >> 1;

        // invariant: committed groups = phases 0..p+1; keep <=1 pending => p landed
        asm volatile("cp.async.wait_group 1;\n");
        __syncthreads();

        if (h == 0) {
            const u64 b0 = s_b[0];
            const u64 b1 = s_b[1];
            #pragma unroll
            for (int rw = 0; rw < 2; rw++)
                #pragma unroll
                for (int q = 0; q < 4; q++) { acc0[rw][q] = b0; acc1[rw][q] = b1; }
        }

        // compute ci-half h from buffer h
        {
            const float* pl0 = plbase + h * HBUF;
            const u64*   wci = s_w + h * 36;
            #pragma unroll 1
            for (int cc = 0; cc < 2; cc++) {
                #pragma unroll
                for (int ky = 0; ky < 3; ky++) {
                    const ulonglong2* wp = (const ulonglong2*)(wci + ky * 6);
                    const ulonglong2 wv0 = wp[0], wv1 = wp[1], wv2 = wp[2];

                    #pragma unroll
                    for (int rw = 0; rw < 2; rw++) {
                        float4 B = *(const float4*)(pl0 + (rw + ky) * SROW_P);

                        float A = __shfl_up_sync(0xffffffffu, B.w, 1);
                        float E = __shfl_down_sync(0xffffffffu, B.x, 1);
                        if (lane == 0)  A = 0.0f;
                        if (lane == 31) E = 0.0f;

                        u64 dv[6];
                        dv[0] = pk(A, A);
                        dv[1] = pk(B.x, B.x);
                        dv[2] = pk(B.y, B.y);
                        dv[3] = pk(B.z, B.z);
                        dv[4] = pk(B.w, B.w);
                        dv[5] = pk(E, E);

                        #pragma unroll
                        for (int q = 0; q < 4; q++) {
                            ffma2(acc0[rw][q], wv0.x, dv[q]);
                            ffma2(acc1[rw][q], wv0.y, dv[q]);
                            ffma2(acc0[rw][q], wv1.x, dv[q + 1]);
                            ffma2(acc1[rw][q], wv1.y, dv[q + 1]);
                            ffma2(acc0[rw][q], wv2.x, dv[q + 2]);
                            ffma2(acc1[rw][q], wv2.y, dv[q + 2]);
                        }
                    }
                }
                pl0 += PLANE_P;
                wci += 18;
            }
        }

        if (h == 1) {
            // tile t complete: store 2 rows x 4 co
            const int y = (((sup << 2) + t) << 3) + 2 * wrp;
            #pragma unroll
            for (int rw = 0; rw < 2; rw++) {
                float* obase = outg + (long long)(y + rw) * W;
                float l0[4], h0[4], l1[4], h1[4];
                #pragma unroll
                for (int q = 0; q < 4; q++) {
                    upk(acc0[rw][q], l0[q], h0[q]);
                    upk(acc1[rw][q], l1[q], h1[q]);
                }
                *(float4*)(obase)                          = make_float4(l0[0], l0[1], l0[2], l0[3]);
                *(float4*)(obase + (long long) 64 * PLANE) = make_float4(h0[0], h0[1], h0[2], h0[3]);
                *(float4*)(obase + (long long)128 * PLANE) = make_float4(l1[0], l1[1], l1[2], l1[3]);
                *(float4*)(obase + (long long)192 * PLANE) = make_float4(h1[0], h1[1], h1[2], h1[3]);
            }
        }

        __syncthreads();   // all warps done reading buffer h

        // prefetch phase p+2 into buffer h (empty commit at tail keeps invariant)
        if (p + 2 < 2 * NTILE) {
            STAGE_HALF((p + 2) >> 1, h)
        } else {
            asm volatile("cp.async.commit_group;\n");
        }
    }
    #undef STAGE_HALF
}

extern "C" void kernel_launch(void* const* d_in, const int* in_sizes, int n_in,
                              void* d_out, int out_size) {
    const float* x    = (const float*)d_in[0];
    const float* w    = (const float*)d_in[1];
    const float* bias = (const float*)d_in[2];
    float* out        = (float*)d_out;
    (void)in_sizes; (void)n_in; (void)out_size;
    cudaFuncSetAttribute(bdconv_kernel,
                         cudaFuncAttributeMaxDynamicSharedMemorySize, SMEM_BYTES);
    bdconv_kernel<<<32 * 64 * NTILE, THREADS, SMEM_BYTES>>>(x, w, bias, out);
}